// round 16
// baseline (speedup 1.0000x reference)
#include <cuda_runtime.h>

// Problem: B=4, T=4096, WINDOW=1024, MAX_DISP=2.0
// out[b,t] = linear interp of x at s = w[b]*coeff[t] + t (tent kernel collapses),
// out-of-range k dropped.
//
// FINAL KERNEL — converged over 15 measured rounds; latency-bound at the
// single-launch floor (all ncu pipes <0.5%, DRAM 0.1%, ~80 KB total traffic).
// Session-best measurements: 3.97 us ncu (twice), 4.54-4.64 us harness.
//
// Design-space map (each point measured against a prediction):
//   smem tile + BAR + LDS (this)      : 3.97-4.26 us  <- optimum
//   smem tile + warp-scope sync       : 4.22  (barrier scope irrelevant, R11)
//   register window + SHFL            : 5.31  (shuffles > LDS, R13)
//   warp tiles w/ extra instructions  : 4.48  (instruction count rules, R3)
//   scalar direct 2-LDG               : 4.74  (serialized DRAM trips, R1)
//   vector loads / vector stores      : neutral (R4, R15)
//
// Mechanisms:
//  - analytic collapse of the [4,4096,4096] tent-kernel matmul to 2-tap interp
//  - w (float4) load overlapped with the w-independent x-tile prefetch:
//    both cold-DRAM round trips in flight concurrently (-0.8 us, R2)
//  - grid=32 x 128: one block-wide tile serves all 4 batch rows (R6)
//  - branchless epilogue: FSEL weight masks enforce the exact k in [0,T)
//    semantics; clamped smem indices give unconditional memory safety (R7)
//  - coeff folded to one bit-exact FFMA-imm; per-chain stores (R8/R9)

#define T_DIM 4096
#define B_DIM 4
#define BLK   128                // t-range per block = 128; 32 blocks total
#define HALO  64                 // |w*coeff| << 64 for these inputs
#define TILE  (BLK + 2 * HALO)   // 256 floats = 1 KB shared

__global__ void __launch_bounds__(BLK) tvp_kernel(const float4* __restrict__ w4,
                                                  const float* __restrict__ x,
                                                  float* __restrict__ out) {
    __shared__ float sx[TILE];

    const int tid  = threadIdx.x;
    const int t    = blockIdx.x * BLK + tid;   // 0 .. T-1
    const int t0   = t - tid;                  // block's first t
    const int base = t0 - HALO;                // tile covers k in [base, base+TILE)

    // --- issue all independent loads up front (overlap) ---
    float4 wv = __ldg(w4);                     // all 4 w's, one 16B line, broadcast

    {   // cooperative x tile prefetch: 2 coalesced floats per thread, clamped
        int ca = min(max(base + tid,       0), T_DIM - 1);
        int cb = min(max(base + tid + BLK, 0), T_DIM - 1);
        float va = x[ca];                      // independent of w -> overlaps
        float vb = x[cb];
        sx[tid]       = va;
        sx[tid + BLK] = vb;
    }
    __syncthreads();

    // --- dependent math: 4 independent, fully branchless interp chains ---
    // coeff = 2*((t mod 1024)/1024 - 0.5) == (t mod 1024)/512 - 1, exact in fp32
    float wn = (float)(t & 1023);
    float c  = fmaf(wn, 1.0f / 512.0f, -1.0f); // single FFMA-imm, bit-exact
    float tf = (float)t;

    const float wb[4] = {wv.x, wv.y, wv.z, wv.w};

    #pragma unroll
    for (int b = 0; b < B_DIM; b++) {
        float s    = wb[b] * c + tf;           // match reference mul-then-add
        int   k0   = __float2int_rd(s);
        float frac = s - (float)k0;
        int   k1   = k0 + 1;

        // exact k-range enforcement via weight masks (FSEL, no branch)
        float m0 = (k0 >= 0 && k0 < T_DIM) ? (1.0f - frac) : 0.0f;
        float m1 = (k1 >= 0 && k1 < T_DIM) ? frac          : 0.0f;

        // tile reads with clamped smem index (always a valid address)
        int o0 = min(max(k0 - base, 0), TILE - 1);
        int o1 = min(max(k1 - base, 0), TILE - 1);

        // store as soon as this chain resolves (coalesced per warp)
        out[b * T_DIM + t] = fmaf(m0, sx[o0], m1 * sx[o1]);
    }
}

extern "C" void kernel_launch(void* const* d_in, const int* in_sizes, int n_in,
                              void* d_out, int out_size) {
    const float4* w4 = (const float4*)d_in[0];  // [4,1] -> one float4
    const float*  x  = (const float*)d_in[1];   // [1,4096]
    float* out = (float*)d_out;                 // [4,4096,1] = 16384 floats

    const int blocks = T_DIM / BLK;             // 32
    tvp_kernel<<<blocks, BLK>>>(w4, x, out);
}